// round 7
// baseline (speedup 1.0000x reference)
#include <cuda_runtime.h>

#define NN  100000
#define NE  1600000
#define IN_DIM  64
#define HID_DIM 48
#define OUT_DIM 32

#define SCAN_B 512
#define SCAN_NBLK ((NN + SCAN_B - 1) / SCAN_B)

// ---------------------------------------------------------------------------
// Scratch (device globals)
// ---------------------------------------------------------------------------
__device__ float g_h0  [(size_t)NN * HID_DIM];
__device__ float g_out1[(size_t)NN * HID_DIM];
__device__ float g_h1  [(size_t)NN * OUT_DIM];
__device__ float g_dis [NN];
__device__ int2  g_erec[NE];                     // CSR records: (src, bitcast norm)
__device__ int   g_cnt [NN];
__device__ int   g_fill[NN];
__device__ int   g_rowptr[NN + 1];
__device__ int   g_part[NN];
__device__ int   g_bsum[SCAN_NBLK];
__device__ int   g_is64;

// ---------------------------------------------------------------------------
// Zero counters + (block 0, thread 0) dtype detect:
// int64 values < 2^31 ==> all odd int32 words zero.
// ---------------------------------------------------------------------------
__global__ void k_zero(const int* __restrict__ raw, int n) {
    int i = blockIdx.x * blockDim.x + threadIdx.x;
    if (i < n) { g_cnt[i] = 0; g_fill[i] = 0; }
    if (i == 0) {
        int all_zero = 1;
        for (int k = 1; k < 128; k += 2)
            if (raw[k] != 0) { all_zero = 0; break; }
        g_is64 = all_zero;
    }
}

// Count in-degrees straight from the raw buffer.
__global__ void k_count(const void* __restrict__ raw, int e) {
    int i = blockIdx.x * blockDim.x + threadIdx.x;
    if (i >= e) return;
    int d;
    if (g_is64) d = (int)((const long long*)raw)[e + i];
    else        d = ((const int*)raw)[e + i];
    d = min(max(d, 0), NN - 1);
    atomicAdd(&g_cnt[d], 1);
}

// ---------------------------------------------------------------------------
// Exclusive scan of g_cnt -> rowptr pieces; also computes dis (fused).
// ---------------------------------------------------------------------------
__global__ void k_scan1(int n) {
    __shared__ int sh[SCAN_B];
    int i = blockIdx.x * SCAN_B + threadIdx.x;
    int v = (i < n) ? g_cnt[i] : 0;
    if (i < n) g_dis[i] = rsqrtf((float)(v + 1));          // +1 self-loop
    sh[threadIdx.x] = v;
    __syncthreads();
#pragma unroll
    for (int off = 1; off < SCAN_B; off <<= 1) {
        int t = (threadIdx.x >= off) ? sh[threadIdx.x - off] : 0;
        __syncthreads();
        sh[threadIdx.x] += t;
        __syncthreads();
    }
    if (i < n) g_part[i] = sh[threadIdx.x] - v;            // exclusive
    if (threadIdx.x == SCAN_B - 1) g_bsum[blockIdx.x] = sh[SCAN_B - 1];
}

__global__ void k_scan2() {                                 // one block
    __shared__ int sh[SCAN_NBLK];
    int t = threadIdx.x;
    for (int i = t; i < SCAN_NBLK; i += blockDim.x) sh[i] = g_bsum[i];
    __syncthreads();
    if (t == 0) {
        int run = 0;
        for (int i = 0; i < SCAN_NBLK; i++) { int v = sh[i]; sh[i] = run; run += v; }
    }
    __syncthreads();
    for (int i = t; i < SCAN_NBLK; i += blockDim.x) g_bsum[i] = sh[i];
}

__global__ void k_scan3(int n, int e) {
    int i = blockIdx.x * SCAN_B + threadIdx.x;
    if (i < n) g_rowptr[i] = g_part[i] + g_bsum[blockIdx.x];
    if (i == 0) g_rowptr[n] = e;
}

// ---------------------------------------------------------------------------
// CSR fill straight from raw edges: record = (src, norm)
// ---------------------------------------------------------------------------
__global__ void k_fill(const void* __restrict__ raw, int e) {
    int i = blockIdx.x * blockDim.x + threadIdx.x;
    if (i >= e) return;
    int s, d;
    if (g_is64) {
        const long long* p = (const long long*)raw;
        s = (int)p[i];
        d = (int)p[e + i];
    } else {
        const int* p = (const int*)raw;
        s = p[i];
        d = p[e + i];
    }
    s = min(max(s, 0), NN - 1);
    d = min(max(d, 0), NN - 1);
    float nm = g_dis[s] * g_dis[d];
    int pos = g_rowptr[d] + atomicAdd(&g_fill[d], 1);
    g_erec[pos] = make_int2(s, __float_as_int(nm));
}

// ---------------------------------------------------------------------------
// Dense transform: H[n,F] = (relu?)(X[n,K]) @ W[K,F]
// ---------------------------------------------------------------------------
template <int K, int F, bool RELU_IN>
__global__ void k_gemm(const float* __restrict__ X,
                       const float* __restrict__ W,
                       float* __restrict__ H, int n) {
    constexpr int G = F / 4;
    __shared__ float Ws[K * F];
    for (int i = threadIdx.x; i < K * F; i += blockDim.x) Ws[i] = W[i];
    __syncthreads();

    int tid = blockIdx.x * blockDim.x + threadIdx.x;
    int row = tid / G;
    int g   = tid % G;
    if (row >= n) return;

    const float* xr = X + (size_t)row * K;
    float4 acc = make_float4(0.f, 0.f, 0.f, 0.f);
#pragma unroll
    for (int k = 0; k < K; k++) {
        float xv = xr[k];
        if (RELU_IN) xv = fmaxf(xv, 0.f);
        float4 w = *reinterpret_cast<const float4*>(&Ws[k * F + g * 4]);
        acc.x = fmaf(xv, w.x, acc.x);
        acc.y = fmaf(xv, w.y, acc.y);
        acc.z = fmaf(xv, w.z, acc.z);
        acc.w = fmaf(xv, w.w, acc.w);
    }
    *reinterpret_cast<float4*>(&H[(size_t)row * F + g * 4]) = acc;
}

// ---------------------------------------------------------------------------
// CSR gather-aggregate (no atomics), unrolled x2 with dual accumulators:
//   O[v,f] = b[f] + H[v,f]*dis[v]^2 + sum_{(s,nm) in list(v)} H[s,f]*nm
// ---------------------------------------------------------------------------
template <int F>
__global__ void k_aggcsr(const float* __restrict__ H,
                         const float* __restrict__ b,
                         float* __restrict__ O, int n) {
    constexpr int G = F / 4;
    int tid = blockIdx.x * blockDim.x + threadIdx.x;
    int node = tid / G;
    int g    = tid % G;
    if (node >= n) return;

    size_t o = (size_t)node * F + g * 4;
    float ds = g_dis[node];
    float d2 = ds * ds;
    float4 h  = *reinterpret_cast<const float4*>(&H[o]);
    float4 bv = *reinterpret_cast<const float4*>(&b[g * 4]);
    float4 acc0 = make_float4(bv.x + h.x * d2, bv.y + h.y * d2,
                              bv.z + h.z * d2, bv.w + h.w * d2);
    float4 acc1 = make_float4(0.f, 0.f, 0.f, 0.f);

    int beg = g_rowptr[node];
    int end = g_rowptr[node + 1];
    int j = beg;
    for (; j + 2 <= end; j += 2) {
        int2 r0 = g_erec[j];
        int2 r1 = g_erec[j + 1];
        float4 v0 = *reinterpret_cast<const float4*>(&H[(size_t)r0.x * F + g * 4]);
        float4 v1 = *reinterpret_cast<const float4*>(&H[(size_t)r1.x * F + g * 4]);
        float n0 = __int_as_float(r0.y);
        float n1 = __int_as_float(r1.y);
        acc0.x = fmaf(v0.x, n0, acc0.x);
        acc0.y = fmaf(v0.y, n0, acc0.y);
        acc0.z = fmaf(v0.z, n0, acc0.z);
        acc0.w = fmaf(v0.w, n0, acc0.w);
        acc1.x = fmaf(v1.x, n1, acc1.x);
        acc1.y = fmaf(v1.y, n1, acc1.y);
        acc1.z = fmaf(v1.z, n1, acc1.z);
        acc1.w = fmaf(v1.w, n1, acc1.w);
    }
    if (j < end) {
        int2 r = g_erec[j];
        float nm = __int_as_float(r.y);
        float4 v = *reinterpret_cast<const float4*>(&H[(size_t)r.x * F + g * 4]);
        acc0.x = fmaf(v.x, nm, acc0.x);
        acc0.y = fmaf(v.y, nm, acc0.y);
        acc0.z = fmaf(v.z, nm, acc0.z);
        acc0.w = fmaf(v.w, nm, acc0.w);
    }
    acc0.x += acc1.x; acc0.y += acc1.y; acc0.z += acc1.z; acc0.w += acc1.w;
    *reinterpret_cast<float4*>(&O[o]) = acc0;
}

// ---------------------------------------------------------------------------
// Launch
// ---------------------------------------------------------------------------
static inline int cdiv(long long a, int b) { return (int)((a + b - 1) / b); }

extern "C" void kernel_launch(void* const* d_in, const int* in_sizes, int n_in,
                              void* d_out, int out_size) {
    const float* x   = (const float*)d_in[0];
    const void*  ei  = d_in[1];
    const float* W1  = (const float*)d_in[2];
    const float* b1  = (const float*)d_in[3];
    const float* W2  = (const float*)d_in[4];
    const float* b2  = (const float*)d_in[5];
    float*       out = (float*)d_out;

    const int n = in_sizes[0] / IN_DIM;   // 100000
    const int e = in_sizes[1] / 2;        // 1600000

    float *h0, *out1, *h1;
    cudaGetSymbolAddress((void**)&h0,   g_h0);
    cudaGetSymbolAddress((void**)&out1, g_out1);
    cudaGetSymbolAddress((void**)&h1,   g_h1);

    const int T = 256;

    // CSR build (6 launches)
    k_zero <<<cdiv(n, T), T>>>((const int*)ei, n);
    k_count<<<cdiv(e, T), T>>>(ei, e);
    k_scan1<<<SCAN_NBLK, SCAN_B>>>(n);
    k_scan2<<<1, 256>>>();
    k_scan3<<<SCAN_NBLK, SCAN_B>>>(n, e);
    k_fill <<<cdiv(e, T), T>>>(ei, e);

    // Layer 1
    k_gemm<IN_DIM, HID_DIM, false><<<cdiv((long long)n * (HID_DIM / 4), T), T>>>(x, W1, h0, n);
    k_aggcsr<HID_DIM><<<cdiv((long long)n * (HID_DIM / 4), T), T>>>(h0, b1, out1, n);

    // Layer 2
    k_gemm<HID_DIM, OUT_DIM, true><<<cdiv((long long)n * (OUT_DIM / 4), T), T>>>(out1, W2, h1, n);
    k_aggcsr<OUT_DIM><<<cdiv((long long)n * (OUT_DIM / 4), T), T>>>(h1, b2, out, n);
}

// round 8
// speedup vs baseline: 1.5606x; 1.5606x over previous
#include <cuda_runtime.h>

#define NN  100000
#define NE  1600000
#define IN_DIM  64
#define HID_DIM 48
#define OUT_DIM 32

#define SCAN_B 512
#define SCAN_NBLK ((NN + SCAN_B - 1) / SCAN_B)

// ---------------------------------------------------------------------------
// Scratch (device globals)
// ---------------------------------------------------------------------------
__device__ float g_h0  [(size_t)NN * HID_DIM];
__device__ float g_out1[(size_t)NN * HID_DIM];
__device__ float g_h1  [(size_t)NN * OUT_DIM];
__device__ float g_dis [NN];
__device__ int2  g_edge[NE];                     // parsed (src, dst)
__device__ int2  g_erec[NE];                     // CSR records: (src, bitcast norm)
__device__ int   g_cnt [NN];
__device__ int   g_fill[NN];
__device__ int   g_rowptr[NN + 1];
__device__ int   g_part[NN];
__device__ int   g_bsum[SCAN_NBLK];
__device__ int   g_is64;

// ---------------------------------------------------------------------------
// Zero counters + warp-parallel dtype detect (block 0, warp 0):
// int64 values < 2^31 ==> all odd int32 words zero. 32 parallel probes.
// ---------------------------------------------------------------------------
__global__ void k_zero(const int* __restrict__ raw, int n) {
    int i = blockIdx.x * blockDim.x + threadIdx.x;
    if (i < n) { g_cnt[i] = 0; g_fill[i] = 0; }
    if (blockIdx.x == 0 && threadIdx.x < 32) {
        int w = raw[threadIdx.x * 2 + 1];                 // odd int32 words
        unsigned nz = __ballot_sync(0xFFFFFFFFu, w != 0);
        if (threadIdx.x == 0) g_is64 = (nz == 0u);
    }
}

// Parse raw edges -> int2 AND count in-degrees (fused).
__global__ void k_convert(const void* __restrict__ raw, int e) {
    int i = blockIdx.x * blockDim.x + threadIdx.x;
    if (i >= e) return;
    int s, d;
    if (g_is64) {
        const long long* p = (const long long*)raw;
        s = (int)p[i];
        d = (int)p[e + i];
    } else {
        const int* p = (const int*)raw;
        s = p[i];
        d = p[e + i];
    }
    s = min(max(s, 0), NN - 1);                   // defensive clamp (no trap)
    d = min(max(d, 0), NN - 1);
    g_edge[i] = make_int2(s, d);
    atomicAdd(&g_cnt[d], 1);
}

// ---------------------------------------------------------------------------
// Exclusive scan of g_cnt (3 kernels); dis computed in pass 1 (fused).
// ---------------------------------------------------------------------------
__global__ void k_scan1(int n) {
    __shared__ int sh[SCAN_B];
    int i = blockIdx.x * SCAN_B + threadIdx.x;
    int v = (i < n) ? g_cnt[i] : 0;
    if (i < n) g_dis[i] = rsqrtf((float)(v + 1));          // +1 self-loop
    sh[threadIdx.x] = v;
    __syncthreads();
#pragma unroll
    for (int off = 1; off < SCAN_B; off <<= 1) {
        int t = (threadIdx.x >= off) ? sh[threadIdx.x - off] : 0;
        __syncthreads();
        sh[threadIdx.x] += t;
        __syncthreads();
    }
    if (i < n) g_part[i] = sh[threadIdx.x] - v;            // exclusive
    if (threadIdx.x == SCAN_B - 1) g_bsum[blockIdx.x] = sh[SCAN_B - 1];
}

__global__ void k_scan2() {                                 // one block
    __shared__ int sh[SCAN_NBLK];
    int t = threadIdx.x;
    for (int i = t; i < SCAN_NBLK; i += blockDim.x) sh[i] = g_bsum[i];
    __syncthreads();
    if (t == 0) {
        int run = 0;
        for (int i = 0; i < SCAN_NBLK; i++) { int v = sh[i]; sh[i] = run; run += v; }
    }
    __syncthreads();
    for (int i = t; i < SCAN_NBLK; i += blockDim.x) g_bsum[i] = sh[i];
}

__global__ void k_scan3(int n, int e) {
    int i = blockIdx.x * SCAN_B + threadIdx.x;
    if (i < n) g_rowptr[i] = g_part[i] + g_bsum[blockIdx.x];
    if (i == 0) g_rowptr[n] = e;
}

// ---------------------------------------------------------------------------
// CSR fill from parsed edges: record = (src, norm)
// ---------------------------------------------------------------------------
__global__ void k_fill(int e) {
    int i = blockIdx.x * blockDim.x + threadIdx.x;
    if (i >= e) return;
    int2 ed = g_edge[i];
    float nm = g_dis[ed.x] * g_dis[ed.y];
    int pos = g_rowptr[ed.y] + atomicAdd(&g_fill[ed.y], 1);
    g_erec[pos] = make_int2(ed.x, __float_as_int(nm));
}

// ---------------------------------------------------------------------------
// Dense transform: H[n,F] = (relu?)(X[n,K]) @ W[K,F]
// ---------------------------------------------------------------------------
template <int K, int F, bool RELU_IN>
__global__ void k_gemm(const float* __restrict__ X,
                       const float* __restrict__ W,
                       float* __restrict__ H, int n) {
    constexpr int G = F / 4;
    __shared__ float Ws[K * F];
    for (int i = threadIdx.x; i < K * F; i += blockDim.x) Ws[i] = W[i];
    __syncthreads();

    int tid = blockIdx.x * blockDim.x + threadIdx.x;
    int row = tid / G;
    int g   = tid % G;
    if (row >= n) return;

    const float* xr = X + (size_t)row * K;
    float4 acc = make_float4(0.f, 0.f, 0.f, 0.f);
#pragma unroll
    for (int k = 0; k < K; k++) {
        float xv = xr[k];
        if (RELU_IN) xv = fmaxf(xv, 0.f);
        float4 w = *reinterpret_cast<const float4*>(&Ws[k * F + g * 4]);
        acc.x = fmaf(xv, w.x, acc.x);
        acc.y = fmaf(xv, w.y, acc.y);
        acc.z = fmaf(xv, w.z, acc.z);
        acc.w = fmaf(xv, w.w, acc.w);
    }
    *reinterpret_cast<float4*>(&H[(size_t)row * F + g * 4]) = acc;
}

// ---------------------------------------------------------------------------
// CSR gather-aggregate (no atomics) — proven R6 form:
//   O[v,f] = b[f] + H[v,f]*dis[v]^2 + sum_{(s,nm) in list(v)} H[s,f]*nm
// ---------------------------------------------------------------------------
template <int F>
__global__ void k_aggcsr(const float* __restrict__ H,
                         const float* __restrict__ b,
                         float* __restrict__ O, int n) {
    constexpr int G = F / 4;
    int tid = blockIdx.x * blockDim.x + threadIdx.x;
    int node = tid / G;
    int g    = tid % G;
    if (node >= n) return;

    size_t o = (size_t)node * F + g * 4;
    float ds = g_dis[node];
    float d2 = ds * ds;
    float4 h  = *reinterpret_cast<const float4*>(&H[o]);
    float4 bv = *reinterpret_cast<const float4*>(&b[g * 4]);
    float4 acc = make_float4(bv.x + h.x * d2, bv.y + h.y * d2,
                             bv.z + h.z * d2, bv.w + h.w * d2);

    int beg = g_rowptr[node];
    int end = g_rowptr[node + 1];
#pragma unroll 2
    for (int j = beg; j < end; j++) {
        int2 r = g_erec[j];                         // broadcast across G threads
        float nm = __int_as_float(r.y);
        float4 v = *reinterpret_cast<const float4*>(&H[(size_t)r.x * F + g * 4]);
        acc.x = fmaf(v.x, nm, acc.x);
        acc.y = fmaf(v.y, nm, acc.y);
        acc.z = fmaf(v.z, nm, acc.z);
        acc.w = fmaf(v.w, nm, acc.w);
    }
    *reinterpret_cast<float4*>(&O[o]) = acc;
}

// ---------------------------------------------------------------------------
// Launch
// ---------------------------------------------------------------------------
static inline int cdiv(long long a, int b) { return (int)((a + b - 1) / b); }

extern "C" void kernel_launch(void* const* d_in, const int* in_sizes, int n_in,
                              void* d_out, int out_size) {
    const float* x   = (const float*)d_in[0];
    const void*  ei  = d_in[1];
    const float* W1  = (const float*)d_in[2];
    const float* b1  = (const float*)d_in[3];
    const float* W2  = (const float*)d_in[4];
    const float* b2  = (const float*)d_in[5];
    float*       out = (float*)d_out;

    const int n = in_sizes[0] / IN_DIM;   // 100000
    const int e = in_sizes[1] / 2;        // 1600000

    float *h0, *out1, *h1;
    cudaGetSymbolAddress((void**)&h0,   g_h0);
    cudaGetSymbolAddress((void**)&out1, g_out1);
    cudaGetSymbolAddress((void**)&h1,   g_h1);

    const int T = 256;

    // CSR build (5 launches)
    k_zero   <<<cdiv(n, T), T>>>((const int*)ei, n);
    k_convert<<<cdiv(e, T), T>>>(ei, e);
    k_scan1  <<<SCAN_NBLK, SCAN_B>>>(n);
    k_scan2  <<<1, 256>>>();
    k_scan3  <<<SCAN_NBLK, SCAN_B>>>(n, e);
    k_fill   <<<cdiv(e, T), T>>>(e);

    // Layer 1
    k_gemm<IN_DIM, HID_DIM, false><<<cdiv((long long)n * (HID_DIM / 4), T), T>>>(x, W1, h0, n);
    k_aggcsr<HID_DIM><<<cdiv((long long)n * (HID_DIM / 4), T), T>>>(h0, b1, out1, n);

    // Layer 2
    k_gemm<HID_DIM, OUT_DIM, true><<<cdiv((long long)n * (OUT_DIM / 4), T), T>>>(out1, W2, h1, n);
    k_aggcsr<OUT_DIM><<<cdiv((long long)n * (OUT_DIM / 4), T), T>>>(h1, b2, out, n);
}